// round 15
// baseline (speedup 1.0000x reference)
#include <cuda_runtime.h>
#include <math_constants.h>

// ---------------------------------------------------------------------------
// Scratch (static __device__ arrays — no allocation allowed)
// ---------------------------------------------------------------------------
__device__ __align__(16) float g_h1[16 * 64 * 256 * 256];    // 256 MB
__device__ __align__(16) float g_h2[16 * 128 * 128 * 128];   // 128 MB
__device__ __align__(16) float g_h3[16 * 128 * 64 * 64];     //  32 MB
__device__ __align__(16) float g_z [16 * 4 * 64 * 64];       //   1 MB
__device__ __align__(16) float g_w2T[16 * 128 * 64];         // [tap][ic][oc]
__device__ __align__(16) float g_w3T[16 * 128 * 128];
__device__ float g_partial[256];

// ---------------------------------------------------------------------------
// packed f32x2 FMA on raw 64-bit register pairs (two IEEE fp32 FMAs,
// bitwise identical per lane to scalar __fmaf_rn).
// ---------------------------------------------------------------------------
__device__ __forceinline__ void fma2u(unsigned long long& acc,
                                      unsigned long long w,
                                      unsigned long long iv) {
    asm("fma.rn.f32x2 %0, %1, %2, %0;" : "+l"(acc) : "l"(w), "l"(iv));
}

__device__ __forceinline__ unsigned long long dup2(float v) {
    unsigned long long r;
    unsigned int u = __float_as_uint(v);
    asm("mov.b64 %0, {%1, %1};" : "=l"(r) : "r"(u));
    return r;
}

__device__ __forceinline__ void unpack2(unsigned long long a, float& lo, float& hi) {
    unsigned int l, h;
    asm("mov.b64 {%0, %1}, %2;" : "=r"(l), "=r"(h) : "l"(a));
    lo = __uint_as_float(l);
    hi = __uint_as_float(h);
}

// ---------------------------------------------------------------------------
// Weight transpose prepass: w[oc][ic][ky][kx] -> wT[tap][ic][oc], tap = ky*K+kx
// ---------------------------------------------------------------------------
__global__ void transpose_w_k(const float* __restrict__ src, float* __restrict__ dst,
                              int OC, int IC, int KK)
{
    int i = blockIdx.x * 256 + threadIdx.x;
    if (i >= OC * IC * KK) return;
    int t  = i % KK;
    int ic = (i / KK) % IC;
    int oc = i / (KK * IC);
    dst[((size_t)t * IC + ic) * OC + oc] = src[i];
}

// ---------------------------------------------------------------------------
// conv1: [16,1,512,512] -> [16,64,256,256], 4x4 s2 p1, relu. IC=1.
// FROZEN (bit-exact): (ky,kx) tap order.
// ---------------------------------------------------------------------------
__global__ void __launch_bounds__(256)
conv1_k(const float* __restrict__ in, const float* __restrict__ w,
        const float* __restrict__ bias, float* __restrict__ out)
{
    constexpr int IH = 512, IW = 512, OH = 256, OW = 256, OC = 64;
    constexpr int TH = 16, TW = 16, ITH = 35, ITW = 35;

    __shared__ float s_in[ITH * ITW];
    __shared__ float s_w[OC * 16];

    const int b = blockIdx.z;
    const int tile = blockIdx.x;
    constexpr int TILES_X = OW / TW;
    const int oy0 = (tile / TILES_X) * TH;
    const int ox0 = (tile % TILES_X) * TW;

    const int tid = threadIdx.x;
    const int sg = tid & 63, g = tid >> 6;
    const int py = (sg >> 3) * 2, px = (sg & 7) * 2;

    const float* inp = in + (size_t)b * IH * IW;
    const int iy0 = oy0 * 2 - 1, ix0 = ox0 * 2 - 1;

    for (int i = tid; i < ITH * ITW; i += 256) {
        int ly = i / ITW, lx = i % ITW;
        int gy = iy0 + ly, gx = ix0 + lx;
        float v = 0.f;
        if (gy >= 0 && gy < IH && gx >= 0 && gx < IW)
            v = inp[(size_t)gy * IW + gx];
        s_in[i] = v;
    }
    for (int i = tid; i < OC * 16; i += 256) s_w[i] = w[i];
    __syncthreads();

    float acc[16 * 4];
#pragma unroll
    for (int i = 0; i < 64; ++i) acc[i] = 0.f;

#pragma unroll
    for (int ky = 0; ky < 4; ++ky) {
#pragma unroll
        for (int kx = 0; kx < 4; ++kx) {
            float iv[4];
#pragma unroll
            for (int d = 0; d < 4; ++d) {
                int dy = d >> 1, dx = d & 1;
                iv[d] = s_in[((py + dy) * 2 + ky) * ITW + (px + dx) * 2 + kx];
            }
#pragma unroll
            for (int j = 0; j < 16; ++j) {
                float wv = s_w[(g * 16 + j) * 16 + ky * 4 + kx];
#pragma unroll
                for (int d = 0; d < 4; ++d)
                    acc[j * 4 + d] = __fmaf_rn(wv, iv[d], acc[j * 4 + d]);
            }
        }
    }

#pragma unroll
    for (int j = 0; j < 16; ++j) {
        const int oc = g * 16 + j;
        const float bv = bias[oc];
#pragma unroll
        for (int d = 0; d < 4; ++d) {
            int dy = d >> 1, dx = d & 1;
            float v = fmaxf(__fadd_rn(acc[j * 4 + d], bv), 0.f);
            out[(((size_t)b * OC + oc) * OH + oy0 + py + dy) * OW + ox0 + px + dx] = v;
        }
    }
}

// ---------------------------------------------------------------------------
// conv2 / conv3: 4x4 s2 p1, relu. (ky,kx,ic) order, ic innermost, single FMA
// chain per output — bit-frozen per-output rounding.
// R15 schedule: same 8x32 tile / 16oc x 4pos as R14, but register-lean:
// weights fed to FFMA2 directly from LDS.128 register pairs (no unpack),
// accs held as 64-bit pairs, 3 CTAs/SM target.
// ---------------------------------------------------------------------------
template<int IC, int OC, int IH, int IW, int OH, int OW, int NBUF>
__global__ void __launch_bounds__(256, 3)
conv_p4_k(const float* __restrict__ in, const float* __restrict__ wT,
          const float* __restrict__ bias, float* __restrict__ out)
{
    constexpr int OCB = 64, OCT = 16, TH = 8, TW = 32, K = 4, S = 2, PAD = 1;

    __shared__ float s_w[NBUF * IC * OCB];   // [buf][ic][oc-slice]

    const int b   = blockIdx.z;
    const int oc0 = blockIdx.y * OCB;
    constexpr int TILES_X = OW / TW;
    const int oy0 = ((int)blockIdx.x / TILES_X) * TH;
    const int ox0 = ((int)blockIdx.x % TILES_X) * TW;

    const int tid  = threadIdx.x;
    const int oxo  = tid & 31;                 // lane x within tile
    const int half = (tid >> 5) & 1;           // row half: rows 0-3 or 4-7
    const int g    = tid >> 6;                 // oc group (0..3)
    const int ox   = ox0 + oxo;
    const int oyb  = oy0 + half * 4;           // 4 consecutive rows per thread

    unsigned long long acc[8][4];              // [oc-pair][row p]
#pragma unroll
    for (int j = 0; j < 8; ++j)
#pragma unroll
        for (int p = 0; p < 4; ++p) acc[j][p] = 0ull;

    const float* inb = in + (size_t)b * IC * IH * IW;

    if (NBUF == 2) {
        const float* wt = wT + (size_t)0 * IC * OC + oc0;
#pragma unroll 4
        for (int i = tid; i < IC * OCB; i += 256) {
            int ic = i >> 6, o = i & 63;
            s_w[i] = wt[(size_t)ic * OC + o];
        }
        __syncthreads();
    }

    for (int tap = 0; tap < K * K; ++tap) {
        const int ky = tap >> 2, kx = tap & 3;

        const float* sw;
        if (NBUF == 2) {
            if (tap + 1 < K * K) {
                const float* wt = wT + (size_t)(tap + 1) * IC * OC + oc0;
                float* dst = &s_w[((tap + 1) & 1) * IC * OCB];
#pragma unroll 4
                for (int i = tid; i < IC * OCB; i += 256) {
                    int ic = i >> 6, o = i & 63;
                    dst[i] = wt[(size_t)ic * OC + o];
                }
            }
            sw = &s_w[(tap & 1) * IC * OCB];
        } else {
            __syncthreads();
            const float* wt = wT + (size_t)tap * IC * OC + oc0;
#pragma unroll 4
            for (int i = tid; i < IC * OCB; i += 256) {
                int ic = i >> 6, o = i & 63;
                s_w[i] = wt[(size_t)ic * OC + o];
            }
            __syncthreads();
            sw = s_w;
        }

        const int ixA = ox * S - PAD + kx;
        const bool vx = (unsigned)ixA < (unsigned)IW;
        const int iyA = oyb * S - PAD + ky;          // row for p=0; p adds 2*p
        bool vy[4];
#pragma unroll
        for (int p = 0; p < 4; ++p)
            vy[p] = (unsigned)(iyA + 2 * p) < (unsigned)IH;
        const float* pcol = inb + (ptrdiff_t)iyA * IW + ixA;

        for (int ic = 0; ic < IC; ++ic) {
            const float* p = pcol + (size_t)ic * IH * IW;
            float v0 = (vy[0] && vx) ? p[0] : 0.f;
            float v1 = (vy[1] && vx) ? p[(ptrdiff_t)2 * IW] : 0.f;
            float v2 = (vy[2] && vx) ? p[(ptrdiff_t)4 * IW] : 0.f;
            float v3 = (vy[3] && vx) ? p[(ptrdiff_t)6 * IW] : 0.f;

            // 16 weights = 4 LDS.128; 64-bit halves ARE the f2 oc-pairs.
            const ulonglong2* wrow =
                reinterpret_cast<const ulonglong2*>(&sw[ic * OCB + g * OCT]);
            const ulonglong2 u0 = wrow[0];
            const ulonglong2 u1 = wrow[1];
            const ulonglong2 u2 = wrow[2];
            const ulonglong2 u3 = wrow[3];

            {
                unsigned long long iv = dup2(v0);
                fma2u(acc[0][0], u0.x, iv); fma2u(acc[1][0], u0.y, iv);
                fma2u(acc[2][0], u1.x, iv); fma2u(acc[3][0], u1.y, iv);
                fma2u(acc[4][0], u2.x, iv); fma2u(acc[5][0], u2.y, iv);
                fma2u(acc[6][0], u3.x, iv); fma2u(acc[7][0], u3.y, iv);
            }
            {
                unsigned long long iv = dup2(v1);
                fma2u(acc[0][1], u0.x, iv); fma2u(acc[1][1], u0.y, iv);
                fma2u(acc[2][1], u1.x, iv); fma2u(acc[3][1], u1.y, iv);
                fma2u(acc[4][1], u2.x, iv); fma2u(acc[5][1], u2.y, iv);
                fma2u(acc[6][1], u3.x, iv); fma2u(acc[7][1], u3.y, iv);
            }
            {
                unsigned long long iv = dup2(v2);
                fma2u(acc[0][2], u0.x, iv); fma2u(acc[1][2], u0.y, iv);
                fma2u(acc[2][2], u1.x, iv); fma2u(acc[3][2], u1.y, iv);
                fma2u(acc[4][2], u2.x, iv); fma2u(acc[5][2], u2.y, iv);
                fma2u(acc[6][2], u3.x, iv); fma2u(acc[7][2], u3.y, iv);
            }
            {
                unsigned long long iv = dup2(v3);
                fma2u(acc[0][3], u0.x, iv); fma2u(acc[1][3], u0.y, iv);
                fma2u(acc[2][3], u1.x, iv); fma2u(acc[3][3], u1.y, iv);
                fma2u(acc[4][3], u2.x, iv); fma2u(acc[5][3], u2.y, iv);
                fma2u(acc[6][3], u3.x, iv); fma2u(acc[7][3], u3.y, iv);
            }
        }

        if (NBUF == 2) __syncthreads();
    }

#pragma unroll
    for (int j = 0; j < 8; ++j) {
        const int oc = oc0 + g * OCT + 2 * j;
        const float b0 = bias[oc], b1 = bias[oc + 1];
#pragma unroll
        for (int p = 0; p < 4; ++p) {
            float lo, hi;
            unpack2(acc[j][p], lo, hi);
            float v0 = fmaxf(__fadd_rn(lo, b0), 0.f);
            float v1 = fmaxf(__fadd_rn(hi, b1), 0.f);
            size_t o0 = (((size_t)b * OC + oc) * OH + oyb + p) * OW + ox;
            out[o0] = v0;
            out[o0 + (size_t)OH * OW] = v1;
        }
    }
}

// ---------------------------------------------------------------------------
// conv4: [16,128,64,64] -> [16,4,64,64], 3x3 s1 p1, no relu.
// FROZEN (bit-exact): (ic,ky,kx) order, ic OUTERMOST, single chain.
// ---------------------------------------------------------------------------
__global__ void __launch_bounds__(256)
conv4_k(const float* __restrict__ in, const float* __restrict__ w,
        const float* __restrict__ bias, float* __restrict__ out)
{
    constexpr int IC = 128, OC = 4, HW = 64;

    __shared__ float s_w[OC * IC * 9];   // raw [oc][ic][tap], 18 KB

    const int b = blockIdx.z;
    const int oy0 = ((int)blockIdx.x >> 1) * 32;
    const int ox0 = ((int)blockIdx.x & 1) * 32;

    const int tid = threadIdx.x;
    const int py = (tid >> 4) * 2, px = (tid & 15) * 2;
    const int oy = oy0 + py, ox = ox0 + px;

    for (int i = tid; i < OC * IC * 9; i += 256) s_w[i] = w[i];
    __syncthreads();

    float acc[4][4];   // [oc][pos]
#pragma unroll
    for (int o = 0; o < 4; ++o)
#pragma unroll
        for (int d = 0; d < 4; ++d) acc[o][d] = 0.f;

    const float* inb = in + (size_t)b * IC * HW * HW;

    const int iy0 = oy - 1, ix0 = ox - 1;
    bool vr[4], vc[4];
#pragma unroll
    for (int r = 0; r < 4; ++r) vr[r] = (unsigned)(iy0 + r) < (unsigned)HW;
#pragma unroll
    for (int c = 0; c < 4; ++c) vc[c] = (unsigned)(ix0 + c) < (unsigned)HW;

    for (int ic = 0; ic < IC; ++ic) {
        const float* p = inb + (size_t)ic * HW * HW + (ptrdiff_t)iy0 * HW + ix0;
        float patch[4][4];
#pragma unroll
        for (int r = 0; r < 4; ++r)
#pragma unroll
            for (int c = 0; c < 4; ++c)
                patch[r][c] = (vr[r] && vc[c]) ? p[(ptrdiff_t)r * HW + c] : 0.f;

        const float* wic0 = &s_w[ic * 9];      // oc stride = IC*9
#pragma unroll
        for (int ky = 0; ky < 3; ++ky) {
#pragma unroll
            for (int kx = 0; kx < 3; ++kx) {
                float iv[4];
#pragma unroll
                for (int d = 0; d < 4; ++d) {
                    int dy = d >> 1, dx = d & 1;
                    iv[d] = patch[ky + dy][kx + dx];
                }
#pragma unroll
                for (int o = 0; o < 4; ++o) {
                    float wv = wic0[(size_t)o * IC * 9 + ky * 3 + kx];
#pragma unroll
                    for (int d = 0; d < 4; ++d)
                        acc[o][d] = __fmaf_rn(wv, iv[d], acc[o][d]);
                }
            }
        }
    }

#pragma unroll
    for (int o = 0; o < 4; ++o) {
        const float bv = bias[o];
#pragma unroll
        for (int d = 0; d < 4; ++d) {
            int dy = d >> 1, dx = d & 1;
            out[(((size_t)b * OC + o) * HW + oy + dy) * HW + ox + dx] =
                __fadd_rn(acc[o][d], bv);
        }
    }
}

// ---------------------------------------------------------------------------
// VQ — FROZEN (bit-exact). ze = FFMA chain; zz/ee = rounded squares +
// sequential adds; d = (zz - 2 ze) + ee; strict '<' keeps first min.
// ---------------------------------------------------------------------------
__global__ void __launch_bounds__(256)
vq_k(const float* __restrict__ z, const float* __restrict__ emb,
     float* __restrict__ out)
{
    __shared__ float4 s_e[512];
    __shared__ float  s_ee[512];
    __shared__ float  s_red[8];

    const int tid = threadIdx.x;
    for (int i = tid; i < 512; i += 256) {
        float4 e = reinterpret_cast<const float4*>(emb)[i];
        s_e[i]  = e;
        s_ee[i] = __fadd_rn(__fadd_rn(__fadd_rn(__fmul_rn(e.x, e.x),
                    __fmul_rn(e.y, e.y)), __fmul_rn(e.z, e.z)), __fmul_rn(e.w, e.w));
    }
    __syncthreads();

    const int r = blockIdx.x * 256 + tid;
    const float4 zv = reinterpret_cast<const float4*>(z)[r];
    const float zz = __fadd_rn(__fadd_rn(__fadd_rn(__fmul_rn(zv.x, zv.x),
                       __fmul_rn(zv.y, zv.y)), __fmul_rn(zv.z, zv.z)),
                       __fmul_rn(zv.w, zv.w));

    float dmin = CUDART_INF_F;
    int imin = 0;
#pragma unroll 4
    for (int c = 0; c < 512; ++c) {
        float4 e = s_e[c];
        float ze = __fmul_rn(zv.x, e.x);
        ze = __fmaf_rn(zv.y, e.y, ze);
        ze = __fmaf_rn(zv.z, e.z, ze);
        ze = __fmaf_rn(zv.w, e.w, ze);
        float d = __fadd_rn(__fsub_rn(zz, __fmul_rn(2.f, ze)), s_ee[c]);
        if (d < dmin) { dmin = d; imin = c; }
    }

    const float4 q = s_e[imin];
    float dx = __fsub_rn(q.x, zv.x), dy = __fsub_rn(q.y, zv.y);
    float dz = __fsub_rn(q.z, zv.z), dw = __fsub_rn(q.w, zv.w);
    float4 o;
    o.x = __fadd_rn(zv.x, dx); o.y = __fadd_rn(zv.y, dy);
    o.z = __fadd_rn(zv.z, dz); o.w = __fadd_rn(zv.w, dw);
    reinterpret_cast<float4*>(out)[r] = o;
    out[262145 + r] = (float)imin;

    float s = ((dx * dx + dy * dy) + dz * dz) + dw * dw;
#pragma unroll
    for (int off = 16; off; off >>= 1)
        s += __shfl_down_sync(0xffffffffu, s, off);
    if ((tid & 31) == 0) s_red[tid >> 5] = s;
    __syncthreads();
    if (tid == 0) {
        float t = 0.f;
#pragma unroll
        for (int i = 0; i < 8; ++i) t += s_red[i];
        g_partial[blockIdx.x] = t;
    }
}

__global__ void finish_k(float* __restrict__ out)
{
    __shared__ float sr[256];
    sr[threadIdx.x] = g_partial[threadIdx.x];
    __syncthreads();
#pragma unroll
    for (int s = 128; s; s >>= 1) {
        if (threadIdx.x < s) sr[threadIdx.x] += sr[threadIdx.x + s];
        __syncthreads();
    }
    if (threadIdx.x == 0)
        out[262144] = 1.25f * sr[0] * (1.0f / 262144.0f);
}

// ---------------------------------------------------------------------------
// Launch. inputs: x, w1, b1, w2, b2, w3, b3, w4, b4, emb
// output: [z_q_st (262144) | loss (1) | idx (65536)] float32
// ---------------------------------------------------------------------------
extern "C" void kernel_launch(void* const* d_in, const int* in_sizes, int n_in,
                              void* d_out, int out_size)
{
    (void)in_sizes; (void)n_in; (void)out_size;
    const float* x   = (const float*)d_in[0];
    const float* w1  = (const float*)d_in[1];
    const float* b1  = (const float*)d_in[2];
    const float* w2  = (const float*)d_in[3];
    const float* b2  = (const float*)d_in[4];
    const float* w3  = (const float*)d_in[5];
    const float* b3  = (const float*)d_in[6];
    const float* w4  = (const float*)d_in[7];
    const float* b4  = (const float*)d_in[8];
    const float* emb = (const float*)d_in[9];
    float* out = (float*)d_out;

    void *p1, *p2, *p3, *pz, *pw2, *pw3;
    cudaGetSymbolAddress(&p1, g_h1);
    cudaGetSymbolAddress(&p2, g_h2);
    cudaGetSymbolAddress(&p3, g_h3);
    cudaGetSymbolAddress(&pz, g_z);
    cudaGetSymbolAddress(&pw2, g_w2T);
    cudaGetSymbolAddress(&pw3, g_w3T);
    float* h1  = (float*)p1;
    float* h2  = (float*)p2;
    float* h3  = (float*)p3;
    float* z   = (float*)pz;
    float* w2T = (float*)pw2;
    float* w3T = (float*)pw3;

    // weight transposes: w[oc][ic][t] -> wT[t][ic][oc]  (conv2/conv3 only)
    transpose_w_k<<<(128 * 64 * 16 + 255) / 256, 256>>>(w2, w2T, 128, 64, 16);
    transpose_w_k<<<(128 * 128 * 16 + 255) / 256, 256>>>(w3, w3T, 128, 128, 16);

    // conv1: [16,1,512,512] -> [16,64,256,256]
    conv1_k<<<dim3(256, 1, 16), 256>>>(x, w1, b1, h1);
    // conv2: [16,64,256,256] -> [16,128,128,128]  tile 8x32, double-buffered
    conv_p4_k<64, 128, 256, 256, 128, 128, 2>
        <<<dim3(64, 2, 16), 256>>>(h1, w2T, b2, h2);
    // conv3: [16,128,128,128] -> [16,128,64,64]  tile 8x32, single buffer
    conv_p4_k<128, 128, 128, 128, 64, 64, 1>
        <<<dim3(16, 2, 16), 256>>>(h2, w3T, b3, h3);
    // conv4: [16,128,64,64] -> [16,4,64,64]  (ic,ky,kx) single chain — frozen
    conv4_k<<<dim3(4, 1, 16), 256>>>(h3, w4, b4, z);

    vq_k<<<256, 256>>>(z, emb, out);
    finish_k<<<1, 256>>>(out);
}

// round 16
// speedup vs baseline: 2.5814x; 2.5814x over previous
#include <cuda_runtime.h>
#include <math_constants.h>

// ---------------------------------------------------------------------------
// Scratch (static __device__ arrays — no allocation allowed)
// ---------------------------------------------------------------------------
__device__ __align__(16) float g_h1[16 * 64 * 256 * 256];    // 256 MB
__device__ __align__(16) float g_h2[16 * 128 * 128 * 128];   // 128 MB
__device__ __align__(16) float g_h3[16 * 128 * 64 * 64];     //  32 MB
__device__ __align__(16) float g_z [16 * 4 * 64 * 64];       //   1 MB
__device__ __align__(16) float g_w2T[16 * 128 * 64];         // [tap][ic][oc]
__device__ __align__(16) float g_w3T[16 * 128 * 128];
__device__ float g_partial[256];

// ---------------------------------------------------------------------------
// packed f32x2 FMA on raw 64-bit register pairs (two IEEE fp32 FMAs,
// bitwise identical per lane to scalar __fmaf_rn).
// ---------------------------------------------------------------------------
__device__ __forceinline__ void fma2u(unsigned long long& acc,
                                      unsigned long long w,
                                      unsigned long long iv) {
    asm("fma.rn.f32x2 %0, %1, %2, %0;" : "+l"(acc) : "l"(w), "l"(iv));
}

__device__ __forceinline__ unsigned long long dup2(float v) {
    unsigned long long r;
    unsigned int u = __float_as_uint(v);
    asm("mov.b64 %0, {%1, %1};" : "=l"(r) : "r"(u));
    return r;
}

__device__ __forceinline__ void unpack2(unsigned long long a, float& lo, float& hi) {
    unsigned int l, h;
    asm("mov.b64 {%0, %1}, %2;" : "=r"(l), "=r"(h) : "l"(a));
    lo = __uint_as_float(l);
    hi = __uint_as_float(h);
}

// ---------------------------------------------------------------------------
// Weight transpose prepass: w[oc][ic][ky][kx] -> wT[tap][ic][oc], tap = ky*K+kx
// ---------------------------------------------------------------------------
__global__ void transpose_w_k(const float* __restrict__ src, float* __restrict__ dst,
                              int OC, int IC, int KK)
{
    int i = blockIdx.x * 256 + threadIdx.x;
    if (i >= OC * IC * KK) return;
    int t  = i % KK;
    int ic = (i / KK) % IC;
    int oc = i / (KK * IC);
    dst[((size_t)t * IC + ic) * OC + oc] = src[i];
}

// ---------------------------------------------------------------------------
// conv1: [16,1,512,512] -> [16,64,256,256], 4x4 s2 p1, relu. IC=1.
// FROZEN (bit-exact): (ky,kx) tap order.
// ---------------------------------------------------------------------------
__global__ void __launch_bounds__(256)
conv1_k(const float* __restrict__ in, const float* __restrict__ w,
        const float* __restrict__ bias, float* __restrict__ out)
{
    constexpr int IH = 512, IW = 512, OH = 256, OW = 256, OC = 64;
    constexpr int TH = 16, TW = 16, ITH = 35, ITW = 35;

    __shared__ float s_in[ITH * ITW];
    __shared__ float s_w[OC * 16];

    const int b = blockIdx.z;
    const int tile = blockIdx.x;
    constexpr int TILES_X = OW / TW;
    const int oy0 = (tile / TILES_X) * TH;
    const int ox0 = (tile % TILES_X) * TW;

    const int tid = threadIdx.x;
    const int sg = tid & 63, g = tid >> 6;
    const int py = (sg >> 3) * 2, px = (sg & 7) * 2;

    const float* inp = in + (size_t)b * IH * IW;
    const int iy0 = oy0 * 2 - 1, ix0 = ox0 * 2 - 1;

    for (int i = tid; i < ITH * ITW; i += 256) {
        int ly = i / ITW, lx = i % ITW;
        int gy = iy0 + ly, gx = ix0 + lx;
        float v = 0.f;
        if (gy >= 0 && gy < IH && gx >= 0 && gx < IW)
            v = inp[(size_t)gy * IW + gx];
        s_in[i] = v;
    }
    for (int i = tid; i < OC * 16; i += 256) s_w[i] = w[i];
    __syncthreads();

    float acc[16 * 4];
#pragma unroll
    for (int i = 0; i < 64; ++i) acc[i] = 0.f;

#pragma unroll
    for (int ky = 0; ky < 4; ++ky) {
#pragma unroll
        for (int kx = 0; kx < 4; ++kx) {
            float iv[4];
#pragma unroll
            for (int d = 0; d < 4; ++d) {
                int dy = d >> 1, dx = d & 1;
                iv[d] = s_in[((py + dy) * 2 + ky) * ITW + (px + dx) * 2 + kx];
            }
#pragma unroll
            for (int j = 0; j < 16; ++j) {
                float wv = s_w[(g * 16 + j) * 16 + ky * 4 + kx];
#pragma unroll
                for (int d = 0; d < 4; ++d)
                    acc[j * 4 + d] = __fmaf_rn(wv, iv[d], acc[j * 4 + d]);
            }
        }
    }

#pragma unroll
    for (int j = 0; j < 16; ++j) {
        const int oc = g * 16 + j;
        const float bv = bias[oc];
#pragma unroll
        for (int d = 0; d < 4; ++d) {
            int dy = d >> 1, dx = d & 1;
            float v = fmaxf(__fadd_rn(acc[j * 4 + d], bv), 0.f);
            out[(((size_t)b * OC + oc) * OH + oy0 + py + dy) * OW + ox0 + px + dx] = v;
        }
    }
}

// ---------------------------------------------------------------------------
// conv2 / conv3: 4x4 s2 p1, relu. (ky,kx,ic) order, ic innermost, single FMA
// chain per output — bit-frozen per-output rounding.
// R16 schedule: R14's 8x32 tile / 16oc x 4pos, PLUS:
//   - software-pipelined input loads (prefetch ic+1 before ic's FMAs)
//   - weights fed to FFMA2 directly from LDS.128 64-bit halves (no unpack)
//   - accs as 64-bit pairs; __launch_bounds__(256,2) (no forced occupancy)
// ---------------------------------------------------------------------------
template<int IC, int OC, int IH, int IW, int OH, int OW, int NBUF>
__global__ void __launch_bounds__(256, 2)
conv_p4_k(const float* __restrict__ in, const float* __restrict__ wT,
          const float* __restrict__ bias, float* __restrict__ out)
{
    constexpr int OCB = 64, OCT = 16, TH = 8, TW = 32, K = 4, S = 2, PAD = 1;

    __shared__ float s_w[NBUF * IC * OCB];   // [buf][ic][oc-slice]

    const int b   = blockIdx.z;
    const int oc0 = blockIdx.y * OCB;
    constexpr int TILES_X = OW / TW;
    const int oy0 = ((int)blockIdx.x / TILES_X) * TH;
    const int ox0 = ((int)blockIdx.x % TILES_X) * TW;

    const int tid  = threadIdx.x;
    const int oxo  = tid & 31;                 // lane x within tile
    const int half = (tid >> 5) & 1;           // row half: rows 0-3 or 4-7
    const int g    = tid >> 6;                 // oc group (0..3)
    const int ox   = ox0 + oxo;
    const int oyb  = oy0 + half * 4;           // 4 consecutive rows per thread

    unsigned long long acc[8][4];              // [oc-pair][row p]
#pragma unroll
    for (int j = 0; j < 8; ++j)
#pragma unroll
        for (int p = 0; p < 4; ++p) acc[j][p] = 0ull;

    const float* inb = in + (size_t)b * IC * IH * IW;

    if (NBUF == 2) {
        const float* wt = wT + (size_t)0 * IC * OC + oc0;
#pragma unroll 4
        for (int i = tid; i < IC * OCB; i += 256) {
            int ic = i >> 6, o = i & 63;
            s_w[i] = wt[(size_t)ic * OC + o];
        }
        __syncthreads();
    }

    for (int tap = 0; tap < K * K; ++tap) {
        const int ky = tap >> 2, kx = tap & 3;

        const float* sw;
        if (NBUF == 2) {
            if (tap + 1 < K * K) {
                const float* wt = wT + (size_t)(tap + 1) * IC * OC + oc0;
                float* dst = &s_w[((tap + 1) & 1) * IC * OCB];
#pragma unroll 4
                for (int i = tid; i < IC * OCB; i += 256) {
                    int ic = i >> 6, o = i & 63;
                    dst[i] = wt[(size_t)ic * OC + o];
                }
            }
            sw = &s_w[(tap & 1) * IC * OCB];
        } else {
            __syncthreads();
            const float* wt = wT + (size_t)tap * IC * OC + oc0;
#pragma unroll 4
            for (int i = tid; i < IC * OCB; i += 256) {
                int ic = i >> 6, o = i & 63;
                s_w[i] = wt[(size_t)ic * OC + o];
            }
            __syncthreads();
            sw = s_w;
        }

        const int ixA = ox * S - PAD + kx;
        const bool vx = (unsigned)ixA < (unsigned)IW;
        const int iyA = oyb * S - PAD + ky;          // row for p=0; p adds 2*p
        bool vy[4];
#pragma unroll
        for (int p = 0; p < 4; ++p)
            vy[p] = (unsigned)(iyA + 2 * p) < (unsigned)IH;
        const float* pcol = inb + (ptrdiff_t)iyA * IW + ixA;

        // --- software-pipelined ic loop: prefetch ic+1, compute ic ---
        float n0, n1, n2, n3;
        {
            const float* p = pcol;
            n0 = (vy[0] && vx) ? p[0] : 0.f;
            n1 = (vy[1] && vx) ? p[(ptrdiff_t)2 * IW] : 0.f;
            n2 = (vy[2] && vx) ? p[(ptrdiff_t)4 * IW] : 0.f;
            n3 = (vy[3] && vx) ? p[(ptrdiff_t)6 * IW] : 0.f;
        }

#pragma unroll 2
        for (int ic = 0; ic < IC; ++ic) {
            const float v0 = n0, v1 = n1, v2 = n2, v3 = n3;
            if (ic + 1 < IC) {
                const float* p = pcol + (size_t)(ic + 1) * IH * IW;
                n0 = (vy[0] && vx) ? p[0] : 0.f;
                n1 = (vy[1] && vx) ? p[(ptrdiff_t)2 * IW] : 0.f;
                n2 = (vy[2] && vx) ? p[(ptrdiff_t)4 * IW] : 0.f;
                n3 = (vy[3] && vx) ? p[(ptrdiff_t)6 * IW] : 0.f;
            }

            // 16 weights = 4 LDS.128; 64-bit halves ARE the f2 oc-pairs.
            const ulonglong2* wrow =
                reinterpret_cast<const ulonglong2*>(&sw[ic * OCB + g * OCT]);
            const ulonglong2 u0 = wrow[0];
            const ulonglong2 u1 = wrow[1];
            const ulonglong2 u2 = wrow[2];
            const ulonglong2 u3 = wrow[3];

            {
                unsigned long long iv = dup2(v0);
                fma2u(acc[0][0], u0.x, iv); fma2u(acc[1][0], u0.y, iv);
                fma2u(acc[2][0], u1.x, iv); fma2u(acc[3][0], u1.y, iv);
                fma2u(acc[4][0], u2.x, iv); fma2u(acc[5][0], u2.y, iv);
                fma2u(acc[6][0], u3.x, iv); fma2u(acc[7][0], u3.y, iv);
            }
            {
                unsigned long long iv = dup2(v1);
                fma2u(acc[0][1], u0.x, iv); fma2u(acc[1][1], u0.y, iv);
                fma2u(acc[2][1], u1.x, iv); fma2u(acc[3][1], u1.y, iv);
                fma2u(acc[4][1], u2.x, iv); fma2u(acc[5][1], u2.y, iv);
                fma2u(acc[6][1], u3.x, iv); fma2u(acc[7][1], u3.y, iv);
            }
            {
                unsigned long long iv = dup2(v2);
                fma2u(acc[0][2], u0.x, iv); fma2u(acc[1][2], u0.y, iv);
                fma2u(acc[2][2], u1.x, iv); fma2u(acc[3][2], u1.y, iv);
                fma2u(acc[4][2], u2.x, iv); fma2u(acc[5][2], u2.y, iv);
                fma2u(acc[6][2], u3.x, iv); fma2u(acc[7][2], u3.y, iv);
            }
            {
                unsigned long long iv = dup2(v3);
                fma2u(acc[0][3], u0.x, iv); fma2u(acc[1][3], u0.y, iv);
                fma2u(acc[2][3], u1.x, iv); fma2u(acc[3][3], u1.y, iv);
                fma2u(acc[4][3], u2.x, iv); fma2u(acc[5][3], u2.y, iv);
                fma2u(acc[6][3], u3.x, iv); fma2u(acc[7][3], u3.y, iv);
            }
        }

        if (NBUF == 2) __syncthreads();
    }

#pragma unroll
    for (int j = 0; j < 8; ++j) {
        const int oc = oc0 + g * OCT + 2 * j;
        const float b0 = bias[oc], b1 = bias[oc + 1];
#pragma unroll
        for (int p = 0; p < 4; ++p) {
            float lo, hi;
            unpack2(acc[j][p], lo, hi);
            float v0 = fmaxf(__fadd_rn(lo, b0), 0.f);
            float v1 = fmaxf(__fadd_rn(hi, b1), 0.f);
            size_t o0 = (((size_t)b * OC + oc) * OH + oyb + p) * OW + ox;
            out[o0] = v0;
            out[o0 + (size_t)OH * OW] = v1;
        }
    }
}

// ---------------------------------------------------------------------------
// conv4: [16,128,64,64] -> [16,4,64,64], 3x3 s1 p1, no relu.
// FROZEN (bit-exact): (ic,ky,kx) order, ic OUTERMOST, single chain.
// ---------------------------------------------------------------------------
__global__ void __launch_bounds__(256)
conv4_k(const float* __restrict__ in, const float* __restrict__ w,
        const float* __restrict__ bias, float* __restrict__ out)
{
    constexpr int IC = 128, OC = 4, HW = 64;

    __shared__ float s_w[OC * IC * 9];   // raw [oc][ic][tap], 18 KB

    const int b = blockIdx.z;
    const int oy0 = ((int)blockIdx.x >> 1) * 32;
    const int ox0 = ((int)blockIdx.x & 1) * 32;

    const int tid = threadIdx.x;
    const int py = (tid >> 4) * 2, px = (tid & 15) * 2;
    const int oy = oy0 + py, ox = ox0 + px;

    for (int i = tid; i < OC * IC * 9; i += 256) s_w[i] = w[i];
    __syncthreads();

    float acc[4][4];   // [oc][pos]
#pragma unroll
    for (int o = 0; o < 4; ++o)
#pragma unroll
        for (int d = 0; d < 4; ++d) acc[o][d] = 0.f;

    const float* inb = in + (size_t)b * IC * HW * HW;

    const int iy0 = oy - 1, ix0 = ox - 1;
    bool vr[4], vc[4];
#pragma unroll
    for (int r = 0; r < 4; ++r) vr[r] = (unsigned)(iy0 + r) < (unsigned)HW;
#pragma unroll
    for (int c = 0; c < 4; ++c) vc[c] = (unsigned)(ix0 + c) < (unsigned)HW;

    for (int ic = 0; ic < IC; ++ic) {
        const float* p = inb + (size_t)ic * HW * HW + (ptrdiff_t)iy0 * HW + ix0;
        float patch[4][4];
#pragma unroll
        for (int r = 0; r < 4; ++r)
#pragma unroll
            for (int c = 0; c < 4; ++c)
                patch[r][c] = (vr[r] && vc[c]) ? p[(ptrdiff_t)r * HW + c] : 0.f;

        const float* wic0 = &s_w[ic * 9];      // oc stride = IC*9
#pragma unroll
        for (int ky = 0; ky < 3; ++ky) {
#pragma unroll
            for (int kx = 0; kx < 3; ++kx) {
                float iv[4];
#pragma unroll
                for (int d = 0; d < 4; ++d) {
                    int dy = d >> 1, dx = d & 1;
                    iv[d] = patch[ky + dy][kx + dx];
                }
#pragma unroll
                for (int o = 0; o < 4; ++o) {
                    float wv = wic0[(size_t)o * IC * 9 + ky * 3 + kx];
#pragma unroll
                    for (int d = 0; d < 4; ++d)
                        acc[o][d] = __fmaf_rn(wv, iv[d], acc[o][d]);
                }
            }
        }
    }

#pragma unroll
    for (int o = 0; o < 4; ++o) {
        const float bv = bias[o];
#pragma unroll
        for (int d = 0; d < 4; ++d) {
            int dy = d >> 1, dx = d & 1;
            out[(((size_t)b * OC + o) * HW + oy + dy) * HW + ox + dx] =
                __fadd_rn(acc[o][d], bv);
        }
    }
}

// ---------------------------------------------------------------------------
// VQ — FROZEN (bit-exact). ze = FFMA chain; zz/ee = rounded squares +
// sequential adds; d = (zz - 2 ze) + ee; strict '<' keeps first min.
// ---------------------------------------------------------------------------
__global__ void __launch_bounds__(256)
vq_k(const float* __restrict__ z, const float* __restrict__ emb,
     float* __restrict__ out)
{
    __shared__ float4 s_e[512];
    __shared__ float  s_ee[512];
    __shared__ float  s_red[8];

    const int tid = threadIdx.x;
    for (int i = tid; i < 512; i += 256) {
        float4 e = reinterpret_cast<const float4*>(emb)[i];
        s_e[i]  = e;
        s_ee[i] = __fadd_rn(__fadd_rn(__fadd_rn(__fmul_rn(e.x, e.x),
                    __fmul_rn(e.y, e.y)), __fmul_rn(e.z, e.z)), __fmul_rn(e.w, e.w));
    }
    __syncthreads();

    const int r = blockIdx.x * 256 + tid;
    const float4 zv = reinterpret_cast<const float4*>(z)[r];
    const float zz = __fadd_rn(__fadd_rn(__fadd_rn(__fmul_rn(zv.x, zv.x),
                       __fmul_rn(zv.y, zv.y)), __fmul_rn(zv.z, zv.z)),
                       __fmul_rn(zv.w, zv.w));

    float dmin = CUDART_INF_F;
    int imin = 0;
#pragma unroll 4
    for (int c = 0; c < 512; ++c) {
        float4 e = s_e[c];
        float ze = __fmul_rn(zv.x, e.x);
        ze = __fmaf_rn(zv.y, e.y, ze);
        ze = __fmaf_rn(zv.z, e.z, ze);
        ze = __fmaf_rn(zv.w, e.w, ze);
        float d = __fadd_rn(__fsub_rn(zz, __fmul_rn(2.f, ze)), s_ee[c]);
        if (d < dmin) { dmin = d; imin = c; }
    }

    const float4 q = s_e[imin];
    float dx = __fsub_rn(q.x, zv.x), dy = __fsub_rn(q.y, zv.y);
    float dz = __fsub_rn(q.z, zv.z), dw = __fsub_rn(q.w, zv.w);
    float4 o;
    o.x = __fadd_rn(zv.x, dx); o.y = __fadd_rn(zv.y, dy);
    o.z = __fadd_rn(zv.z, dz); o.w = __fadd_rn(zv.w, dw);
    reinterpret_cast<float4*>(out)[r] = o;
    out[262145 + r] = (float)imin;

    float s = ((dx * dx + dy * dy) + dz * dz) + dw * dw;
#pragma unroll
    for (int off = 16; off; off >>= 1)
        s += __shfl_down_sync(0xffffffffu, s, off);
    if ((tid & 31) == 0) s_red[tid >> 5] = s;
    __syncthreads();
    if (tid == 0) {
        float t = 0.f;
#pragma unroll
        for (int i = 0; i < 8; ++i) t += s_red[i];
        g_partial[blockIdx.x] = t;
    }
}

__global__ void finish_k(float* __restrict__ out)
{
    __shared__ float sr[256];
    sr[threadIdx.x] = g_partial[threadIdx.x];
    __syncthreads();
#pragma unroll
    for (int s = 128; s; s >>= 1) {
        if (threadIdx.x < s) sr[threadIdx.x] += sr[threadIdx.x + s];
        __syncthreads();
    }
    if (threadIdx.x == 0)
        out[262144] = 1.25f * sr[0] * (1.0f / 262144.0f);
}

// ---------------------------------------------------------------------------
// Launch. inputs: x, w1, b1, w2, b2, w3, b3, w4, b4, emb
// output: [z_q_st (262144) | loss (1) | idx (65536)] float32
// ---------------------------------------------------------------------------
extern "C" void kernel_launch(void* const* d_in, const int* in_sizes, int n_in,
                              void* d_out, int out_size)
{
    (void)in_sizes; (void)n_in; (void)out_size;
    const float* x   = (const float*)d_in[0];
    const float* w1  = (const float*)d_in[1];
    const float* b1  = (const float*)d_in[2];
    const float* w2  = (const float*)d_in[3];
    const float* b2  = (const float*)d_in[4];
    const float* w3  = (const float*)d_in[5];
    const float* b3  = (const float*)d_in[6];
    const float* w4  = (const float*)d_in[7];
    const float* b4  = (const float*)d_in[8];
    const float* emb = (const float*)d_in[9];
    float* out = (float*)d_out;

    void *p1, *p2, *p3, *pz, *pw2, *pw3;
    cudaGetSymbolAddress(&p1, g_h1);
    cudaGetSymbolAddress(&p2, g_h2);
    cudaGetSymbolAddress(&p3, g_h3);
    cudaGetSymbolAddress(&pz, g_z);
    cudaGetSymbolAddress(&pw2, g_w2T);
    cudaGetSymbolAddress(&pw3, g_w3T);
    float* h1  = (float*)p1;
    float* h2  = (float*)p2;
    float* h3  = (float*)p3;
    float* z   = (float*)pz;
    float* w2T = (float*)pw2;
    float* w3T = (float*)pw3;

    // weight transposes: w[oc][ic][t] -> wT[t][ic][oc]  (conv2/conv3 only)
    transpose_w_k<<<(128 * 64 * 16 + 255) / 256, 256>>>(w2, w2T, 128, 64, 16);
    transpose_w_k<<<(128 * 128 * 16 + 255) / 256, 256>>>(w3, w3T, 128, 128, 16);

    // conv1: [16,1,512,512] -> [16,64,256,256]
    conv1_k<<<dim3(256, 1, 16), 256>>>(x, w1, b1, h1);
    // conv2: [16,64,256,256] -> [16,128,128,128]  tile 8x32, double-buffered
    conv_p4_k<64, 128, 256, 256, 128, 128, 2>
        <<<dim3(64, 2, 16), 256>>>(h1, w2T, b2, h2);
    // conv3: [16,128,128,128] -> [16,128,64,64]  tile 8x32, single buffer
    conv_p4_k<128, 128, 128, 128, 64, 64, 1>
        <<<dim3(16, 2, 16), 256>>>(h2, w3T, b3, h3);
    // conv4: [16,128,64,64] -> [16,4,64,64]  (ic,ky,kx) single chain — frozen
    conv4_k<<<dim3(4, 1, 16), 256>>>(h3, w4, b4, z);

    vq_k<<<256, 256>>>(z, emb, out);
    finish_k<<<1, 256>>>(out);
}

// round 17
// speedup vs baseline: 2.9141x; 1.1289x over previous
#include <cuda_runtime.h>
#include <math_constants.h>

// ---------------------------------------------------------------------------
// Scratch (static __device__ arrays — no allocation allowed)
// ---------------------------------------------------------------------------
__device__ __align__(16) float g_h1[16 * 64 * 256 * 256];    // 256 MB
__device__ __align__(16) float g_h2[16 * 128 * 128 * 128];   // 128 MB
__device__ __align__(16) float g_h3[16 * 128 * 64 * 64];     //  32 MB
__device__ __align__(16) float g_z [16 * 4 * 64 * 64];       //   1 MB
__device__ __align__(16) float g_w2T[16 * 128 * 64];         // [tap][ic][oc]
__device__ __align__(16) float g_w3T[16 * 128 * 128];
__device__ float g_partial[256];

// ---------------------------------------------------------------------------
// packed f32x2 FMA on raw 64-bit register pairs (two IEEE fp32 FMAs,
// bitwise identical per lane to scalar __fmaf_rn).
// ---------------------------------------------------------------------------
__device__ __forceinline__ void fma2u(unsigned long long& acc,
                                      unsigned long long w,
                                      unsigned long long iv) {
    asm("fma.rn.f32x2 %0, %1, %2, %0;" : "+l"(acc) : "l"(w), "l"(iv));
}

__device__ __forceinline__ unsigned long long dup2(float v) {
    unsigned long long r;
    unsigned int u = __float_as_uint(v);
    asm("mov.b64 %0, {%1, %1};" : "=l"(r) : "r"(u));
    return r;
}

__device__ __forceinline__ void unpack2(unsigned long long a, float& lo, float& hi) {
    unsigned int l, h;
    asm("mov.b64 {%0, %1}, %2;" : "=r"(l), "=r"(h) : "l"(a));
    lo = __uint_as_float(l);
    hi = __uint_as_float(h);
}

// ---------------------------------------------------------------------------
// Weight transpose prepass: w[oc][ic][ky][kx] -> wT[tap][ic][oc], tap = ky*K+kx
// ---------------------------------------------------------------------------
__global__ void transpose_w_k(const float* __restrict__ src, float* __restrict__ dst,
                              int OC, int IC, int KK)
{
    int i = blockIdx.x * 256 + threadIdx.x;
    if (i >= OC * IC * KK) return;
    int t  = i % KK;
    int ic = (i / KK) % IC;
    int oc = i / (KK * IC);
    dst[((size_t)t * IC + ic) * OC + oc] = src[i];
}

// ---------------------------------------------------------------------------
// conv1: [16,1,512,512] -> [16,64,256,256], 4x4 s2 p1, relu. IC=1.
// FROZEN (bit-exact): (ky,kx) tap order.
// ---------------------------------------------------------------------------
__global__ void __launch_bounds__(256)
conv1_k(const float* __restrict__ in, const float* __restrict__ w,
        const float* __restrict__ bias, float* __restrict__ out)
{
    constexpr int IH = 512, IW = 512, OH = 256, OW = 256, OC = 64;
    constexpr int TH = 16, TW = 16, ITH = 35, ITW = 35;

    __shared__ float s_in[ITH * ITW];
    __shared__ float s_w[OC * 16];

    const int b = blockIdx.z;
    const int tile = blockIdx.x;
    constexpr int TILES_X = OW / TW;
    const int oy0 = (tile / TILES_X) * TH;
    const int ox0 = (tile % TILES_X) * TW;

    const int tid = threadIdx.x;
    const int sg = tid & 63, g = tid >> 6;
    const int py = (sg >> 3) * 2, px = (sg & 7) * 2;

    const float* inp = in + (size_t)b * IH * IW;
    const int iy0 = oy0 * 2 - 1, ix0 = ox0 * 2 - 1;

    for (int i = tid; i < ITH * ITW; i += 256) {
        int ly = i / ITW, lx = i % ITW;
        int gy = iy0 + ly, gx = ix0 + lx;
        float v = 0.f;
        if (gy >= 0 && gy < IH && gx >= 0 && gx < IW)
            v = inp[(size_t)gy * IW + gx];
        s_in[i] = v;
    }
    for (int i = tid; i < OC * 16; i += 256) s_w[i] = w[i];
    __syncthreads();

    float acc[16 * 4];
#pragma unroll
    for (int i = 0; i < 64; ++i) acc[i] = 0.f;

#pragma unroll
    for (int ky = 0; ky < 4; ++ky) {
#pragma unroll
        for (int kx = 0; kx < 4; ++kx) {
            float iv[4];
#pragma unroll
            for (int d = 0; d < 4; ++d) {
                int dy = d >> 1, dx = d & 1;
                iv[d] = s_in[((py + dy) * 2 + ky) * ITW + (px + dx) * 2 + kx];
            }
#pragma unroll
            for (int j = 0; j < 16; ++j) {
                float wv = s_w[(g * 16 + j) * 16 + ky * 4 + kx];
#pragma unroll
                for (int d = 0; d < 4; ++d)
                    acc[j * 4 + d] = __fmaf_rn(wv, iv[d], acc[j * 4 + d]);
            }
        }
    }

#pragma unroll
    for (int j = 0; j < 16; ++j) {
        const int oc = g * 16 + j;
        const float bv = bias[oc];
#pragma unroll
        for (int d = 0; d < 4; ++d) {
            int dy = d >> 1, dx = d & 1;
            float v = fmaxf(__fadd_rn(acc[j * 4 + d], bv), 0.f);
            out[(((size_t)b * OC + oc) * OH + oy0 + py + dy) * OW + ox0 + px + dx] = v;
        }
    }
}

// ---------------------------------------------------------------------------
// conv2 / conv3: 4x4 s2 p1, relu. (ky,kx,ic) order, ic innermost, single FMA
// chain per output — bit-frozen per-output rounding.
// R17 schedule = R14 (8x32 tile, 16oc x 4pos, smem weights) with:
//   - weights fed to FFMA2 directly from LDS.128 64-bit halves (no unpack)
//   - ic loop unrolled 4x (deeper LDG batching, ~4-ic effective prefetch)
// ---------------------------------------------------------------------------
template<int IC, int OC, int IH, int IW, int OH, int OW, int NBUF>
__global__ void __launch_bounds__(256, 2)
conv_p4_k(const float* __restrict__ in, const float* __restrict__ wT,
          const float* __restrict__ bias, float* __restrict__ out)
{
    constexpr int OCB = 64, OCT = 16, TH = 8, TW = 32, K = 4, S = 2, PAD = 1;

    __shared__ float s_w[NBUF * IC * OCB];   // [buf][ic][oc-slice]

    const int b   = blockIdx.z;
    const int oc0 = blockIdx.y * OCB;
    constexpr int TILES_X = OW / TW;
    const int oy0 = ((int)blockIdx.x / TILES_X) * TH;
    const int ox0 = ((int)blockIdx.x % TILES_X) * TW;

    const int tid  = threadIdx.x;
    const int oxo  = tid & 31;                 // lane x within tile
    const int half = (tid >> 5) & 1;           // row half: rows 0-3 or 4-7
    const int g    = tid >> 6;                 // oc group (0..3)
    const int ox   = ox0 + oxo;
    const int oyb  = oy0 + half * 4;           // 4 consecutive rows per thread

    unsigned long long acc[8][4];              // [oc-pair][row p]
#pragma unroll
    for (int j = 0; j < 8; ++j)
#pragma unroll
        for (int p = 0; p < 4; ++p) acc[j][p] = 0ull;

    const float* inb = in + (size_t)b * IC * IH * IW;

    if (NBUF == 2) {
        const float* wt = wT + (size_t)0 * IC * OC + oc0;
#pragma unroll 4
        for (int i = tid; i < IC * OCB; i += 256) {
            int ic = i >> 6, o = i & 63;
            s_w[i] = wt[(size_t)ic * OC + o];
        }
        __syncthreads();
    }

    for (int tap = 0; tap < K * K; ++tap) {
        const int ky = tap >> 2, kx = tap & 3;

        const float* sw;
        if (NBUF == 2) {
            if (tap + 1 < K * K) {
                const float* wt = wT + (size_t)(tap + 1) * IC * OC + oc0;
                float* dst = &s_w[((tap + 1) & 1) * IC * OCB];
#pragma unroll 4
                for (int i = tid; i < IC * OCB; i += 256) {
                    int ic = i >> 6, o = i & 63;
                    dst[i] = wt[(size_t)ic * OC + o];
                }
            }
            sw = &s_w[(tap & 1) * IC * OCB];
        } else {
            __syncthreads();
            const float* wt = wT + (size_t)tap * IC * OC + oc0;
#pragma unroll 4
            for (int i = tid; i < IC * OCB; i += 256) {
                int ic = i >> 6, o = i & 63;
                s_w[i] = wt[(size_t)ic * OC + o];
            }
            __syncthreads();
            sw = s_w;
        }

        const int ixA = ox * S - PAD + kx;
        const bool vx = (unsigned)ixA < (unsigned)IW;
        const int iyA = oyb * S - PAD + ky;          // row for p=0; p adds 2*p
        bool vy[4];
#pragma unroll
        for (int p = 0; p < 4; ++p)
            vy[p] = (unsigned)(iyA + 2 * p) < (unsigned)IH;
        const float* pcol = inb + (ptrdiff_t)iyA * IW + ixA;

#pragma unroll 4
        for (int ic = 0; ic < IC; ++ic) {
            const float* p = pcol + (size_t)ic * IH * IW;
            float v0 = (vy[0] && vx) ? p[0] : 0.f;
            float v1 = (vy[1] && vx) ? p[(ptrdiff_t)2 * IW] : 0.f;
            float v2 = (vy[2] && vx) ? p[(ptrdiff_t)4 * IW] : 0.f;
            float v3 = (vy[3] && vx) ? p[(ptrdiff_t)6 * IW] : 0.f;

            // 16 weights = 4 LDS.128; 64-bit halves ARE the oc-pairs.
            const ulonglong2* wrow =
                reinterpret_cast<const ulonglong2*>(&sw[ic * OCB + g * OCT]);
            const ulonglong2 u0 = wrow[0];
            const ulonglong2 u1 = wrow[1];
            const ulonglong2 u2 = wrow[2];
            const ulonglong2 u3 = wrow[3];

            {
                unsigned long long iv = dup2(v0);
                fma2u(acc[0][0], u0.x, iv); fma2u(acc[1][0], u0.y, iv);
                fma2u(acc[2][0], u1.x, iv); fma2u(acc[3][0], u1.y, iv);
                fma2u(acc[4][0], u2.x, iv); fma2u(acc[5][0], u2.y, iv);
                fma2u(acc[6][0], u3.x, iv); fma2u(acc[7][0], u3.y, iv);
            }
            {
                unsigned long long iv = dup2(v1);
                fma2u(acc[0][1], u0.x, iv); fma2u(acc[1][1], u0.y, iv);
                fma2u(acc[2][1], u1.x, iv); fma2u(acc[3][1], u1.y, iv);
                fma2u(acc[4][1], u2.x, iv); fma2u(acc[5][1], u2.y, iv);
                fma2u(acc[6][1], u3.x, iv); fma2u(acc[7][1], u3.y, iv);
            }
            {
                unsigned long long iv = dup2(v2);
                fma2u(acc[0][2], u0.x, iv); fma2u(acc[1][2], u0.y, iv);
                fma2u(acc[2][2], u1.x, iv); fma2u(acc[3][2], u1.y, iv);
                fma2u(acc[4][2], u2.x, iv); fma2u(acc[5][2], u2.y, iv);
                fma2u(acc[6][2], u3.x, iv); fma2u(acc[7][2], u3.y, iv);
            }
            {
                unsigned long long iv = dup2(v3);
                fma2u(acc[0][3], u0.x, iv); fma2u(acc[1][3], u0.y, iv);
                fma2u(acc[2][3], u1.x, iv); fma2u(acc[3][3], u1.y, iv);
                fma2u(acc[4][3], u2.x, iv); fma2u(acc[5][3], u2.y, iv);
                fma2u(acc[6][3], u3.x, iv); fma2u(acc[7][3], u3.y, iv);
            }
        }

        if (NBUF == 2) __syncthreads();
    }

#pragma unroll
    for (int j = 0; j < 8; ++j) {
        const int oc = oc0 + g * OCT + 2 * j;
        const float b0 = bias[oc], b1 = bias[oc + 1];
#pragma unroll
        for (int p = 0; p < 4; ++p) {
            float lo, hi;
            unpack2(acc[j][p], lo, hi);
            float v0 = fmaxf(__fadd_rn(lo, b0), 0.f);
            float v1 = fmaxf(__fadd_rn(hi, b1), 0.f);
            size_t o0 = (((size_t)b * OC + oc) * OH + oyb + p) * OW + ox;
            out[o0] = v0;
            out[o0 + (size_t)OH * OW] = v1;
        }
    }
}

// ---------------------------------------------------------------------------
// conv4: [16,128,64,64] -> [16,4,64,64], 3x3 s1 p1, no relu.
// FROZEN (bit-exact): (ic,ky,kx) order, ic OUTERMOST, single chain.
// ---------------------------------------------------------------------------
__global__ void __launch_bounds__(256)
conv4_k(const float* __restrict__ in, const float* __restrict__ w,
        const float* __restrict__ bias, float* __restrict__ out)
{
    constexpr int IC = 128, OC = 4, HW = 64;

    __shared__ float s_w[OC * IC * 9];   // raw [oc][ic][tap], 18 KB

    const int b = blockIdx.z;
    const int oy0 = ((int)blockIdx.x >> 1) * 32;
    const int ox0 = ((int)blockIdx.x & 1) * 32;

    const int tid = threadIdx.x;
    const int py = (tid >> 4) * 2, px = (tid & 15) * 2;
    const int oy = oy0 + py, ox = ox0 + px;

    for (int i = tid; i < OC * IC * 9; i += 256) s_w[i] = w[i];
    __syncthreads();

    float acc[4][4];   // [oc][pos]
#pragma unroll
    for (int o = 0; o < 4; ++o)
#pragma unroll
        for (int d = 0; d < 4; ++d) acc[o][d] = 0.f;

    const float* inb = in + (size_t)b * IC * HW * HW;

    const int iy0 = oy - 1, ix0 = ox - 1;
    bool vr[4], vc[4];
#pragma unroll
    for (int r = 0; r < 4; ++r) vr[r] = (unsigned)(iy0 + r) < (unsigned)HW;
#pragma unroll
    for (int c = 0; c < 4; ++c) vc[c] = (unsigned)(ix0 + c) < (unsigned)HW;

    for (int ic = 0; ic < IC; ++ic) {
        const float* p = inb + (size_t)ic * HW * HW + (ptrdiff_t)iy0 * HW + ix0;
        float patch[4][4];
#pragma unroll
        for (int r = 0; r < 4; ++r)
#pragma unroll
            for (int c = 0; c < 4; ++c)
                patch[r][c] = (vr[r] && vc[c]) ? p[(ptrdiff_t)r * HW + c] : 0.f;

        const float* wic0 = &s_w[ic * 9];      // oc stride = IC*9
#pragma unroll
        for (int ky = 0; ky < 3; ++ky) {
#pragma unroll
            for (int kx = 0; kx < 3; ++kx) {
                float iv[4];
#pragma unroll
                for (int d = 0; d < 4; ++d) {
                    int dy = d >> 1, dx = d & 1;
                    iv[d] = patch[ky + dy][kx + dx];
                }
#pragma unroll
                for (int o = 0; o < 4; ++o) {
                    float wv = wic0[(size_t)o * IC * 9 + ky * 3 + kx];
#pragma unroll
                    for (int d = 0; d < 4; ++d)
                        acc[o][d] = __fmaf_rn(wv, iv[d], acc[o][d]);
                }
            }
        }
    }

#pragma unroll
    for (int o = 0; o < 4; ++o) {
        const float bv = bias[o];
#pragma unroll
        for (int d = 0; d < 4; ++d) {
            int dy = d >> 1, dx = d & 1;
            out[(((size_t)b * OC + o) * HW + oy + dy) * HW + ox + dx] =
                __fadd_rn(acc[o][d], bv);
        }
    }
}

// ---------------------------------------------------------------------------
// VQ — FROZEN (bit-exact). ze = FFMA chain; zz/ee = rounded squares +
// sequential adds; d = (zz - 2 ze) + ee; strict '<' keeps first min.
// ---------------------------------------------------------------------------
__global__ void __launch_bounds__(256)
vq_k(const float* __restrict__ z, const float* __restrict__ emb,
     float* __restrict__ out)
{
    __shared__ float4 s_e[512];
    __shared__ float  s_ee[512];
    __shared__ float  s_red[8];

    const int tid = threadIdx.x;
    for (int i = tid; i < 512; i += 256) {
        float4 e = reinterpret_cast<const float4*>(emb)[i];
        s_e[i]  = e;
        s_ee[i] = __fadd_rn(__fadd_rn(__fadd_rn(__fmul_rn(e.x, e.x),
                    __fmul_rn(e.y, e.y)), __fmul_rn(e.z, e.z)), __fmul_rn(e.w, e.w));
    }
    __syncthreads();

    const int r = blockIdx.x * 256 + tid;
    const float4 zv = reinterpret_cast<const float4*>(z)[r];
    const float zz = __fadd_rn(__fadd_rn(__fadd_rn(__fmul_rn(zv.x, zv.x),
                       __fmul_rn(zv.y, zv.y)), __fmul_rn(zv.z, zv.z)),
                       __fmul_rn(zv.w, zv.w));

    float dmin = CUDART_INF_F;
    int imin = 0;
#pragma unroll 4
    for (int c = 0; c < 512; ++c) {
        float4 e = s_e[c];
        float ze = __fmul_rn(zv.x, e.x);
        ze = __fmaf_rn(zv.y, e.y, ze);
        ze = __fmaf_rn(zv.z, e.z, ze);
        ze = __fmaf_rn(zv.w, e.w, ze);
        float d = __fadd_rn(__fsub_rn(zz, __fmul_rn(2.f, ze)), s_ee[c]);
        if (d < dmin) { dmin = d; imin = c; }
    }

    const float4 q = s_e[imin];
    float dx = __fsub_rn(q.x, zv.x), dy = __fsub_rn(q.y, zv.y);
    float dz = __fsub_rn(q.z, zv.z), dw = __fsub_rn(q.w, zv.w);
    float4 o;
    o.x = __fadd_rn(zv.x, dx); o.y = __fadd_rn(zv.y, dy);
    o.z = __fadd_rn(zv.z, dz); o.w = __fadd_rn(zv.w, dw);
    reinterpret_cast<float4*>(out)[r] = o;
    out[262145 + r] = (float)imin;

    float s = ((dx * dx + dy * dy) + dz * dz) + dw * dw;
#pragma unroll
    for (int off = 16; off; off >>= 1)
        s += __shfl_down_sync(0xffffffffu, s, off);
    if ((tid & 31) == 0) s_red[tid >> 5] = s;
    __syncthreads();
    if (tid == 0) {
        float t = 0.f;
#pragma unroll
        for (int i = 0; i < 8; ++i) t += s_red[i];
        g_partial[blockIdx.x] = t;
    }
}

__global__ void finish_k(float* __restrict__ out)
{
    __shared__ float sr[256];
    sr[threadIdx.x] = g_partial[threadIdx.x];
    __syncthreads();
#pragma unroll
    for (int s = 128; s; s >>= 1) {
        if (threadIdx.x < s) sr[threadIdx.x] += sr[threadIdx.x + s];
        __syncthreads();
    }
    if (threadIdx.x == 0)
        out[262144] = 1.25f * sr[0] * (1.0f / 262144.0f);
}

// ---------------------------------------------------------------------------
// Launch. inputs: x, w1, b1, w2, b2, w3, b3, w4, b4, emb
// output: [z_q_st (262144) | loss (1) | idx (65536)] float32
// ---------------------------------------------------------------------------
extern "C" void kernel_launch(void* const* d_in, const int* in_sizes, int n_in,
                              void* d_out, int out_size)
{
    (void)in_sizes; (void)n_in; (void)out_size;
    const float* x   = (const float*)d_in[0];
    const float* w1  = (const float*)d_in[1];
    const float* b1  = (const float*)d_in[2];
    const float* w2  = (const float*)d_in[3];
    const float* b2  = (const float*)d_in[4];
    const float* w3  = (const float*)d_in[5];
    const float* b3  = (const float*)d_in[6];
    const float* w4  = (const float*)d_in[7];
    const float* b4  = (const float*)d_in[8];
    const float* emb = (const float*)d_in[9];
    float* out = (float*)d_out;

    void *p1, *p2, *p3, *pz, *pw2, *pw3;
    cudaGetSymbolAddress(&p1, g_h1);
    cudaGetSymbolAddress(&p2, g_h2);
    cudaGetSymbolAddress(&p3, g_h3);
    cudaGetSymbolAddress(&pz, g_z);
    cudaGetSymbolAddress(&pw2, g_w2T);
    cudaGetSymbolAddress(&pw3, g_w3T);
    float* h1  = (float*)p1;
    float* h2  = (float*)p2;
    float* h3  = (float*)p3;
    float* z   = (float*)pz;
    float* w2T = (float*)pw2;
    float* w3T = (float*)pw3;

    // weight transposes: w[oc][ic][t] -> wT[t][ic][oc]  (conv2/conv3 only)
    transpose_w_k<<<(128 * 64 * 16 + 255) / 256, 256>>>(w2, w2T, 128, 64, 16);
    transpose_w_k<<<(128 * 128 * 16 + 255) / 256, 256>>>(w3, w3T, 128, 128, 16);

    // conv1: [16,1,512,512] -> [16,64,256,256]
    conv1_k<<<dim3(256, 1, 16), 256>>>(x, w1, b1, h1);
    // conv2: [16,64,256,256] -> [16,128,128,128]  tile 8x32, double-buffered
    conv_p4_k<64, 128, 256, 256, 128, 128, 2>
        <<<dim3(64, 2, 16), 256>>>(h1, w2T, b2, h2);
    // conv3: [16,128,128,128] -> [16,128,64,64]  tile 8x32, single buffer
    conv_p4_k<128, 128, 128, 128, 64, 64, 1>
        <<<dim3(16, 2, 16), 256>>>(h2, w3T, b3, h3);
    // conv4: [16,128,64,64] -> [16,4,64,64]  (ic,ky,kx) single chain — frozen
    conv4_k<<<dim3(4, 1, 16), 256>>>(h3, w4, b4, z);

    vq_k<<<256, 256>>>(z, emb, out);
    finish_k<<<1, 256>>>(out);
}